// round 1
// baseline (speedup 1.0000x reference)
#include <cuda_runtime.h>
#include <stdint.h>

// Algebraic feature expansion:
//   out[:, 0:16]    = x
//   out[:, 16:136]  = all pair products  x[a]*x[b], (a,b) lex order
//   out[:, 136:696] = all triple products x[a]*x[b]*x[c], lex order
// B = 262144 rows, 16 cols in, 696 cols out. Pure HBM-store-bound (~730 MB out).

#define NC    16
#define NPAIR 120
#define NTRI  560
#define OUTC  696          // 16 + 120 + 560
#define Q4    174          // OUTC / 4 (float4 chunks per row)
#define RTILE 8            // rows per block tile (== warps per block)
#define BLK   256

__global__ __launch_bounds__(BLK) void algebraic_expand_kernel(
    const float* __restrict__ x,
    float4* __restrict__ out4,
    int nrows)
{
    // Packed index table: one uint32 per output column: a | b<<8 | c<<16.
    // Unused operand slots point at index 16, which holds 1.0f in the row cache.
    __shared__ __align__(16) uint32_t stab[OUTC];
    // Row cache replicated across all 32 banks: lane L reads xrep[r][a*32 + L]
    // -> bank == L always -> zero bank conflicts for arbitrary per-lane 'a'.
    __shared__ float xrep[RTILE][17 * 32];

    const int t    = threadIdx.x;
    const int lane = t & 31;
    const int warp = t >> 5;

    // ---- Build the packed index table (lex order == itertools.combinations) ----
    for (int col = t; col < OUTC; col += BLK) {
        int a, b, c;
        if (col < NC) {
            a = col; b = 16; c = 16;
        } else if (col < NC + NPAIR) {
            int p = col - NC;
            a = 0;
            for (;; a++) { int cnt = NC - 1 - a; if (p < cnt) break; p -= cnt; }
            b = a + 1 + p;
            c = 16;
        } else {
            int q = col - NC - NPAIR;
            a = 0;
            for (;; a++) {
                int m = NC - 1 - a;               // elements after a
                int cnt = (m * (m - 1)) >> 1;     // C(m, 2)
                if (q < cnt) break;
                q -= cnt;
            }
            b = a + 1;
            for (;; b++) { int cnt = NC - 1 - b; if (q < cnt) break; q -= cnt; }
            c = b + 1 + q;
        }
        stab[col] = (uint32_t)a | ((uint32_t)b << 8) | ((uint32_t)c << 16);
    }

    const uint4* __restrict__ stab4 = reinterpret_cast<const uint4*>(stab);
    const int ntiles = (nrows + RTILE - 1) / RTILE;

    for (int tile = blockIdx.x; tile < ntiles; tile += gridDim.x) {
        const int row0 = tile * RTILE;

        __syncthreads();   // xrep reuse safety (covers first table build too)

        // ---- Load: warp w caches row (row0 + w), replicated across banks ----
        {
            const int gr = row0 + warp;
            const float* xr = x + (size_t)gr * NC;
            if (gr < nrows) {
                #pragma unroll
                for (int a = 0; a < 17; a++) {
                    // all lanes load the same address -> single broadcast transaction
                    float v = (a < NC) ? __ldg(xr + a) : 1.0f;
                    xrep[warp][a * 32 + lane] = v;   // coalesced, conflict-free STS
                }
            }
        }
        __syncthreads();

        // ---- Compute + store: 8 rows * 174 float4 chunks = 1392 work items ----
        for (unsigned w = t; w < (unsigned)(RTILE * Q4); w += BLK) {
            const unsigned row = w / Q4;
            const unsigned q   = w - row * Q4;
            const int gr = row0 + (int)row;
            if (gr >= nrows) break;

            const uint4 pk = stab4[q];               // 1x LDS.128, conflict-free
            const float* xr = &xrep[row][lane];      // bank == lane for every read

            float4 v;
            {
                uint32_t p = pk.x;
                v.x = xr[(p & 255u) * 32] * xr[((p >> 8) & 255u) * 32] * xr[(p >> 16) * 32];
            }
            {
                uint32_t p = pk.y;
                v.y = xr[(p & 255u) * 32] * xr[((p >> 8) & 255u) * 32] * xr[(p >> 16) * 32];
            }
            {
                uint32_t p = pk.z;
                v.z = xr[(p & 255u) * 32] * xr[((p >> 8) & 255u) * 32] * xr[(p >> 16) * 32];
            }
            {
                uint32_t p = pk.w;
                v.w = xr[(p & 255u) * 32] * xr[((p >> 8) & 255u) * 32] * xr[(p >> 16) * 32];
            }

            // consecutive q across lanes -> fully coalesced 16B stores
            out4[(size_t)gr * Q4 + q] = v;
        }
    }
}

extern "C" void kernel_launch(void* const* d_in, const int* in_sizes, int n_in,
                              void* d_out, int out_size)
{
    const float* x = (const float*)d_in[0];
    const int nrows = in_sizes[0] / NC;

    const int ntiles = (nrows + RTILE - 1) / RTILE;
    int grid = 148 * 16;                 // persistent-ish grid-stride (amortize table build)
    if (grid > ntiles) grid = ntiles;

    algebraic_expand_kernel<<<grid, BLK>>>(x, (float4*)d_out, nrows);
}

// round 2
// speedup vs baseline: 1.4202x; 1.4202x over previous
#include <cuda_runtime.h>
#include <stdint.h>

// Algebraic feature expansion:
//   out[:, 0:16]    = x
//   out[:, 16:136]  = pair products  x[a]*x[b]   (lex order)
//   out[:, 136:696] = triple products x[a]*x[b]*x[c] (lex order)
// B=262144 rows, 696 out cols. HBM-store-bound (~730 MB out).
//
// v2: fixed thread<->chunk mapping. Operand indices decoded ONCE per thread
// into registers; per row the inner body is 12 LDS (immediate row offset),
// 8 FMUL, 1 STG.128. Plain padded smem row cache (conflict-free: all lanes
// of a warp read the same row at distinct columns < 32).

#define NC    16
#define NPAIR 120
#define OUTC  696
#define Q4    174          // OUTC / 4
#define RTILE 16           // rows per tile
#define PAD   20           // floats per cached row (16 data + 1.0 dummy + align)
#define BLK   192          // 6 warps; threads [0,174) compute

__global__ __launch_bounds__(BLK) void algebraic_expand_kernel(
    const float* __restrict__ x,
    float4* __restrict__ out4,
    int nrows)
{
    __shared__ __align__(16) uint32_t stab[OUTC];
    __shared__ __align__(16) float xs[RTILE][PAD];

    const int t = threadIdx.x;

    // ---- Build packed index table once (a | b<<8 | c<<16; 16 = dummy -> 1.0) ----
    for (int col = t; col < OUTC; col += BLK) {
        int a, b, c;
        if (col < NC) {
            a = col; b = 16; c = 16;
        } else if (col < NC + NPAIR) {
            int p = col - NC;
            a = 0;
            for (;; a++) { int cnt = NC - 1 - a; if (p < cnt) break; p -= cnt; }
            b = a + 1 + p;
            c = 16;
        } else {
            int q = col - NC - NPAIR;
            a = 0;
            for (;; a++) {
                int m = NC - 1 - a;
                int cnt = (m * (m - 1)) >> 1;     // C(m,2)
                if (q < cnt) break;
                q -= cnt;
            }
            b = a + 1;
            for (;; b++) { int cnt = NC - 1 - b; if (q < cnt) break; q -= cnt; }
            c = b + 1 + q;
        }
        stab[col] = (uint32_t)a | ((uint32_t)b << 8) | ((uint32_t)c << 16);
    }
    __syncthreads();

    // ---- Decode this thread's fixed chunk ONCE into register pointers ----
    const bool active = (t < Q4);
    const float* base = &xs[0][0];
    const float *p0 = base, *p1 = base, *p2 = base, *p3 = base,
                *p4 = base, *p5 = base, *p6 = base, *p7 = base,
                *p8 = base, *p9 = base, *pa = base, *pb = base;
    if (active) {
        uint4 pk = reinterpret_cast<const uint4*>(stab)[t];
        p0 = base + ( pk.x        & 255u);
        p1 = base + ((pk.x >>  8) & 255u);
        p2 = base + ( pk.x >> 16        );
        p3 = base + ( pk.y        & 255u);
        p4 = base + ((pk.y >>  8) & 255u);
        p5 = base + ( pk.y >> 16        );
        p6 = base + ( pk.z        & 255u);
        p7 = base + ((pk.z >>  8) & 255u);
        p8 = base + ( pk.z >> 16        );
        p9 = base + ( pk.w        & 255u);
        pa = base + ((pk.w >>  8) & 255u);
        pb = base + ( pk.w >> 16        );
    }

    const int ntiles = (nrows + RTILE - 1) / RTILE;

    for (int tile = blockIdx.x; tile < ntiles; tile += gridDim.x) {
        const int row0 = tile * RTILE;

        __syncthreads();   // xs reuse safety

        // ---- Coalesced tile load: RTILE*16 floats = 64 float4 ----
        if (t < RTILE * NC / 4) {
            const int r = t >> 2;
            if (row0 + r < nrows) {
                float4 v = reinterpret_cast<const float4*>(
                               x + (size_t)row0 * NC)[t];
                *reinterpret_cast<float4*>(&xs[r][(t & 3) << 2]) = v;
            }
        }
        if (t < RTILE) xs[t][16] = 1.0f;   // dummy operand
        __syncthreads();

        if (!active) continue;

        float4* ob = out4 + (size_t)row0 * Q4 + t;

        if (row0 + RTILE <= nrows) {
            // fast path: full tile, all offsets compile-time immediates
            #pragma unroll
            for (int r = 0; r < RTILE; r++) {
                const int o = r * PAD;
                float4 v;
                v.x = p0[o] * p1[o] * p2[o];
                v.y = p3[o] * p4[o] * p5[o];
                v.z = p6[o] * p7[o] * p8[o];
                v.w = p9[o] * pa[o] * pb[o];
                __stcs(&ob[(size_t)r * Q4], v);
            }
        } else {
            const int rem = nrows - row0;
            for (int r = 0; r < rem; r++) {
                const int o = r * PAD;
                float4 v;
                v.x = p0[o] * p1[o] * p2[o];
                v.y = p3[o] * p4[o] * p5[o];
                v.z = p6[o] * p7[o] * p8[o];
                v.w = p9[o] * pa[o] * pb[o];
                __stcs(&ob[(size_t)r * Q4], v);
            }
        }
    }
}

extern "C" void kernel_launch(void* const* d_in, const int* in_sizes, int n_in,
                              void* d_out, int out_size)
{
    const float* x = (const float*)d_in[0];
    const int nrows = in_sizes[0] / NC;

    const int ntiles = (nrows + RTILE - 1) / RTILE;
    int grid = 148 * 10;
    if (grid > ntiles) grid = ntiles;

    algebraic_expand_kernel<<<grid, BLK>>>(x, (float4*)d_out, nrows);
}